// round 4
// baseline (speedup 1.0000x reference)
#include <cuda_runtime.h>
#include <math.h>

#define NN   64
#define KK   32
#define FF   1024
#define OO   64
#define JJ   33
#define C1c  4
#define F1c  16
#define C2c  32
#define NCLS 10
#define BN_EPS 1e-5f

// ---------------- scratch ----------------
__device__ float g_C[NN * JJ * FF];
__device__ float g_part[8 * NN * JJ * OO];
__device__ float g_O1[NN * JJ * OO];
__device__ float g_Xrow[NN * OO];            // compact x-path rows
__device__ float g_X2[NN * C2c];
__device__ int   g_ipm[NN * FF];
__device__ int   g_ms[NN * FF];
__device__ float g_sgn[NN * FF];
__device__ int   g_cnt[64];
__device__ int   g_cnt2[1];

// ============================================================================
// K1: per-node hybrid bitonic sort of r = s/x. grid=64, block=1024.
// ============================================================================
__global__ void k_sort(const float* __restrict__ x, const float* __restrict__ nb)
{
    int n = blockIdx.x, t = threadIdx.x;
    __shared__ float sk[FF];
    __shared__ int   sp[FF];

    if (n == 0 && t < 64) g_cnt[t] = 0;
    if (n == 0 && t == 64) g_cnt2[0] = 0;

    float xv = x[(size_t)n * FF + t];
    const float* nbb = nb + (size_t)n * KK * FF;
    float s = 0.f;
    #pragma unroll
    for (int k = 0; k < KK; k++) s += nbb[k * FF + t];

    float key = s / xv;
    int   pay = t;
    float myr = key;
    g_sgn[(size_t)n * FF + t] = (xv >= 0.f) ? 1.f : -1.f;

    #pragma unroll
    for (int k = 2; k <= 32; k <<= 1) {
        #pragma unroll
        for (int j = k >> 1; j >= 1; j >>= 1) {
            float ok = __shfl_xor_sync(0xffffffffu, key, j);
            int   op = __shfl_xor_sync(0xffffffffu, pay, j);
            bool keepmin = (((t & k) == 0) == ((t & j) == 0));
            bool take = keepmin ? (ok < key) : (ok > key);
            if (take) { key = ok; pay = op; }
        }
    }
    for (int k = 64; k <= FF; k <<= 1) {
        for (int j = k >> 1; j >= 32; j >>= 1) {
            sk[t] = key; sp[t] = pay;
            __syncthreads();
            float ok = sk[t ^ j]; int op = sp[t ^ j];
            bool keepmin = (((t & k) == 0) == ((t & j) == 0));
            bool take = keepmin ? (ok < key) : (ok > key);
            if (take) { key = ok; pay = op; }
            __syncthreads();
        }
        #pragma unroll
        for (int j = 16; j >= 1; j >>= 1) {
            float ok = __shfl_xor_sync(0xffffffffu, key, j);
            int   op = __shfl_xor_sync(0xffffffffu, pay, j);
            bool keepmin = (((t & k) == 0) == ((t & j) == 0));
            bool take = keepmin ? (ok < key) : (ok > key);
            if (take) { key = ok; pay = op; }
        }
    }

    sk[t] = key;
    g_ipm[(size_t)n * FF + pay] = t;
    __syncthreads();

    float th = -myr;
    int lo = 0, hi = FF;
    #pragma unroll
    for (int it = 0; it < 10; it++) {
        int mid = (lo + hi) >> 1;
        if (sk[mid] < th) lo = mid + 1; else hi = mid;
    }
    g_ms[(size_t)n * FF + t] = lo;
}

// ============================================================================
// K2: columns scan. grid=(11,64), block=256; 3 j's per CTA; serial-4 scan.
// ============================================================================
__global__ void k_cols(const float* __restrict__ x, const float* __restrict__ nb)
{
    int n = blockIdx.y, t = threadIdx.x;
    int j0 = blockIdx.x * 3;
    __shared__ float sc[FF];
    __shared__ float ws[8];

    int   ip[4], mss[4];
    float sg[4];
    #pragma unroll
    for (int u = 0; u < 4; u++) {
        int i = u * 256 + t;
        ip[u]  = g_ipm[(size_t)n * FF + i];
        mss[u] = g_ms [(size_t)n * FF + i];
        sg[u]  = g_sgn[(size_t)n * FF + i];
    }

    int lane = t & 31, wid = t >> 5;

    for (int jj = 0; jj < 3; jj++) {
        int j = j0 + jj;
        const float* col = (j == 0) ? (x + (size_t)n * FF)
                                    : (nb + ((size_t)n * KK + (j - 1)) * FF);
        #pragma unroll
        for (int u = 0; u < 4; u++)
            sc[ip[u]] = col[u * 256 + t] * sg[u];
        __syncthreads();

        float4 q = *(const float4*)&sc[t * 4];
        float s0 = q.x, s1 = s0 + q.y, s2 = s1 + q.z, s3 = s2 + q.w;
        float tot = s3;
        float inc = tot;
        #pragma unroll
        for (int d = 1; d < 32; d <<= 1) {
            float o = __shfl_up_sync(0xffffffffu, inc, d);
            if (lane >= d) inc += o;
        }
        if (lane == 31) ws[wid] = inc;
        __syncthreads();

        float woff = 0.f, T = 0.f;
        #pragma unroll
        for (int w = 0; w < 8; w++) {
            float wv = ws[w];
            T += wv;
            if (w < wid) woff += wv;
        }
        float base = woff + (inc - tot);          // exclusive prefix at 4t
        *(float4*)&sc[t * 4] = make_float4(base + s0, base + s1, base + s2, base + s3);
        __syncthreads();

        float* Cout = g_C + ((size_t)n * JJ + j) * FF;
        #pragma unroll
        for (int u = 0; u < 4; u++) {
            int m = mss[u];
            float P = m ? sc[m - 1] : 0.f;
            Cout[u * 256 + t] = sg[u] * (T - 2.f * P);
        }
        __syncthreads();
    }
}

// ============================================================================
// K3: GEMM + fused split-K reduce + compact x-row sidecar. grid=(33,8), block=256.
// ============================================================================
__global__ void k_gemm(const float* __restrict__ W1)
{
    __shared__ float Cs[64][33];
    __shared__ float Ws[64][33];
    __shared__ int last;
    int mt  = blockIdx.x;
    int ks  = blockIdx.y;
    int tid = threadIdx.x;
    int mg  = tid >> 4;
    int og  = tid & 15;

    float acc[4][4];
    #pragma unroll
    for (int i = 0; i < 4; i++)
        #pragma unroll
        for (int ii = 0; ii < 4; ii++) acc[i][ii] = 0.f;

    int kb0 = ks * (FF / 8);
    for (int kb = kb0; kb < kb0 + (FF / 8); kb += 32) {
        #pragma unroll
        for (int u = 0; u < 8; u++) {
            int e  = u * 256 + tid;
            int ri = e >> 5, kc = e & 31;
            Cs[ri][kc] = g_C[(size_t)(mt * 64 + ri) * FF + kb + kc];
            Ws[ri][kc] = W1 [(size_t)ri * FF + kb + kc];
        }
        __syncthreads();
        #pragma unroll
        for (int kc = 0; kc < 32; kc++) {
            float ca[4], wb[4];
            #pragma unroll
            for (int i = 0; i < 4; i++)  ca[i] = Cs[mg * 4 + i][kc];
            #pragma unroll
            for (int ii = 0; ii < 4; ii++) wb[ii] = Ws[og * 4 + ii][kc];
            #pragma unroll
            for (int i = 0; i < 4; i++)
                #pragma unroll
                for (int ii = 0; ii < 4; ii++)
                    acc[i][ii] += ca[i] * wb[ii];
        }
        __syncthreads();
    }
    float* pb = g_part + (size_t)ks * (NN * JJ * OO) + (size_t)mt * 64 * OO;
    #pragma unroll
    for (int i = 0; i < 4; i++)
        #pragma unroll
        for (int ii = 0; ii < 4; ii++)
            pb[(mg * 4 + i) * OO + og * 4 + ii] = acc[i][ii];

    __threadfence();
    __syncthreads();
    if (tid == 0) last = (atomicAdd(&g_cnt[mt], 1) == 7);
    __syncthreads();
    if (last) {
        __threadfence();
        const float4* ps = (const float4*)g_part;
        float4* po = (float4*)g_O1;
        float4* px = (float4*)g_Xrow;
        for (int i = tid; i < 1024; i += 256) {
            float4 a = make_float4(0.f, 0.f, 0.f, 0.f);
            #pragma unroll
            for (int s = 0; s < 8; s++) {
                float4 p = ps[(size_t)s * (NN * JJ * OO / 4) + mt * 1024 + i];
                a.x += p.x; a.y += p.y; a.z += p.z; a.w += p.w;
            }
            po[mt * 1024 + i] = a;
            int m = mt * 64 + (i >> 4);
            if (m % 33 == 0) px[(m / 33) * 16 + (i & 15)] = a;
        }
    }
}

// ============================================================================
// K4: layer2 + fused final. grid=64, block=256.
// ============================================================================
__global__ void k_layer2(const float* __restrict__ W2,
                         const float* __restrict__ bn1w, const float* __restrict__ bn1b,
                         const float* __restrict__ bn2w, const float* __restrict__ bn2b,
                         const float* __restrict__ lw,  const float* __restrict__ lb,
                         float* __restrict__ out)
{
    int n = blockIdx.x, t = threadIdx.x;
    __shared__ float nbs[KK * 64];
    __shared__ float red[1024];
    __shared__ float tmp[16];
    __shared__ float x1s[64], t2s[64], xa2s[64];
    __shared__ float gm[4], gr[4], cm[4], cr[4];
    __shared__ int last;

    const float4* O1v = (const float4*)g_O1;
    const float4* Xv  = (const float4*)g_Xrow;
    float4* nbsv = (float4*)nbs;

    // neighbor tile load (vectorized, coalesced)
    #pragma unroll
    for (int u = 0; u < 2; u++) {
        int i4 = u * 256 + t;                  // 0..511
        int row = i4 >> 4, c4 = i4 & 15;
        nbsv[i4] = O1v[((size_t)(n * JJ + 1 + row)) * 16 + c4];
    }

    // global x-path stats from compact g_Xrow (dense float4)
    int ch = (t & 15) >> 2;                    // channel of this thread's c4
    float gs1 = 0.f, gs2 = 0.f;
    #pragma unroll
    for (int u = 0; u < 4; u++) {
        float4 q = Xv[u * 256 + t];
        gs1 += q.x + q.y + q.z + q.w;
        gs2 += q.x * q.x + q.y * q.y + q.z * q.z + q.w * q.w;
    }
    __syncthreads();                           // nbs ready

    // per-node neighbor stats (from shared, vectorized)
    float ns1 = 0.f, ns2 = 0.f;
    #pragma unroll
    for (int u = 0; u < 2; u++) {
        float4 q = nbsv[u * 256 + t];
        ns1 += q.x + q.y + q.z + q.w;
        ns2 += q.x * q.x + q.y * q.y + q.z * q.z + q.w * q.w;
    }
    int sic = ((t >> 4) << 2) | (t & 3);       // 0..63 within channel
    red[      ch * 64 + sic] = gs1;
    red[256 + ch * 64 + sic] = gs2;
    red[512 + ch * 64 + sic] = ns1;
    red[768 + ch * 64 + sic] = ns2;
    __syncthreads();

    {   // 4 arrays x 4 channels: serial-4 + width-16 shuffle
        int arr = t >> 6, c = (t >> 4) & 3, l = t & 15;
        int base = arr * 256 + c * 64;
        float v = red[base + l] + red[base + l + 16] + red[base + l + 32] + red[base + l + 48];
        #pragma unroll
        for (int d = 8; d > 0; d >>= 1)
            v += __shfl_down_sync(0xffffffffu, v, d, 16);
        if (l == 0) tmp[arr * 4 + c] = v;
    }
    __syncthreads();
    if (t < 4) {
        float m = tmp[t] / 1024.f;
        gm[t] = m; gr[t] = rsqrtf(tmp[4 + t] / 1024.f - m * m + BN_EPS);
        float m2 = tmp[8 + t] / 512.f;
        cm[t] = m2; cr[t] = rsqrtf(tmp[12 + t] / 512.f - m2 * m2 + BN_EPS);
    }
    __syncthreads();

    if (t < 64) {
        float v = g_Xrow[n * OO + t];
        int c = t >> 4;
        float y = (v - gm[c]) * gr[c] * bn1w[c] + bn1b[c];
        x1s[t] = y / (1.f + fabsf(y));
    }
    #pragma unroll
    for (int u = 0; u < 2; u++) {
        int i4 = u * 256 + t;
        int c = ((i4 & 15) >> 2);
        float4 q = nbsv[i4];
        float sw = cr[c] * bn1w[c];
        float y;
        y = (q.x - cm[c]) * sw + bn1b[c]; q.x = y / (1.f + fabsf(y));
        y = (q.y - cm[c]) * sw + bn1b[c]; q.y = y / (1.f + fabsf(y));
        y = (q.z - cm[c]) * sw + bn1b[c]; q.z = y / (1.f + fabsf(y));
        y = (q.w - cm[c]) * sw + bn1b[c]; q.w = y / (1.f + fabsf(y));
        nbsv[i4] = q;
    }
    __syncthreads();
    if (t < 64) {
        float a = 0.f;
        #pragma unroll
        for (int k = 0; k < KK; k++) a += nbs[k * 64 + t];
        t2s[t] = a;
    }
    __syncthreads();

    {   // xa2s: one (ai,b) pair per thread
        int ai = t >> 4, b = t & 15;
        float sgv[4], ctr[4];
        float den = 1e-7f;
        #pragma unroll
        for (int cc = 0; cc < 4; cc++) {
            float raw = x1s[cc * 16 + ai] * t2s[cc * 16 + b]
                      + x1s[cc * 16 + b]  * t2s[cc * 16 + ai];
            float mag = sqrtf(fmaxf(fabsf(raw), 1e-8f));
            float sg  = (raw > 0.f) ? mag : ((raw < 0.f) ? -mag : 0.f);
            sgv[cc] = sg;
            den += fabsf(sg);
        }
        float inv = 1.f / den;
        #pragma unroll
        for (int cc = 0; cc < 4; cc++)
            ctr[cc] = sgv[cc] * inv * x1s[cc * 16 + b];
        #pragma unroll
        for (int d = 8; d > 0; d >>= 1) {
            #pragma unroll
            for (int cc = 0; cc < 4; cc++)
                ctr[cc] += __shfl_down_sync(0xffffffffu, ctr[cc], d, 16);
        }
        if (b == 0) {
            #pragma unroll
            for (int cc = 0; cc < 4; cc++) xa2s[cc * 16 + ai] = ctr[cc];
        }
    }
    __syncthreads();

    {   // W2 matvec
        int o = t >> 3, seg = t & 7;
        float acc = 0.f;
        #pragma unroll
        for (int i = seg * 8; i < seg * 8 + 8; i++)
            acc += W2[o * 64 + i] * xa2s[i];
        #pragma unroll
        for (int d = 4; d > 0; d >>= 1)
            acc += __shfl_down_sync(0xffffffffu, acc, d, 8);
        if (seg == 0) g_X2[n * C2c + o] = acc;
    }

    __threadfence();
    __syncthreads();
    if (t == 0) last = (atomicAdd(&g_cnt2[0], 1) == NN - 1);
    __syncthreads();
    if (!last) return;
    __threadfence();

    float* z = nbs;
    for (int i = t; i < NN * C2c; i += 256) z[i] = g_X2[i];
    __syncthreads();

    {
        int q = t & 31, g = t >> 5;
        float s1 = 0.f, s2 = 0.f;
        #pragma unroll
        for (int nn = g * 8; nn < g * 8 + 8; nn++) {
            float v = z[nn * C2c + q];
            s1 += v; s2 += v * v;
        }
        red[q * 8 + g] = s1; red[256 + q * 8 + g] = s2;
    }
    __syncthreads();
    __shared__ float qm[C2c], qr[C2c];
    if (t < C2c) {
        float s1 = 0.f, s2 = 0.f;
        #pragma unroll
        for (int g = 0; g < 8; g++) { s1 += red[t * 8 + g]; s2 += red[256 + t * 8 + g]; }
        float m = s1 / 64.f;
        qm[t] = m; qr[t] = rsqrtf(s2 / 64.f - m * m + BN_EPS);
    }
    __syncthreads();
    for (int i = t; i < NN * C2c; i += 256) {
        int q = i & 31;
        float y = (z[i] - qm[q]) * qr[q] * bn2w[q] + bn2b[q];
        z[i] = y / (1.f + fabsf(y));
    }
    __syncthreads();
    for (int i = t; i < NN * NCLS; i += 256) {
        int nn = i / NCLS, cls = i - nn * NCLS;
        float acc = lb[cls];
        #pragma unroll
        for (int q = 0; q < C2c; q++) acc += z[nn * C2c + q] * lw[cls * C2c + q];
        out[i] = acc;
    }
}

// ============================================================================
extern "C" void kernel_launch(void* const* d_in, const int* in_sizes, int n_in,
                              void* d_out, int out_size)
{
    const float* x    = (const float*)d_in[0];
    const float* nb   = (const float*)d_in[1];
    const float* W1   = (const float*)d_in[2];
    const float* W2   = (const float*)d_in[3];
    const float* bn1w = (const float*)d_in[4];
    const float* bn1b = (const float*)d_in[5];
    const float* bn2w = (const float*)d_in[6];
    const float* bn2b = (const float*)d_in[7];
    const float* lw   = (const float*)d_in[8];
    const float* lb   = (const float*)d_in[9];
    float* out = (float*)d_out;

    k_sort<<<NN, 1024>>>(x, nb);
    dim3 gc(11, NN);
    k_cols<<<gc, 256>>>(x, nb);
    dim3 gg(33, 8);
    k_gemm<<<gg, 256>>>(W1);
    k_layer2<<<NN, 256>>>(W2, bn1w, bn1b, bn2w, bn2b, lw, lb, out);
}

// round 5
// speedup vs baseline: 1.0667x; 1.0667x over previous
#include <cuda_runtime.h>
#include <math.h>

#define NN   64
#define KK   32
#define FF   1024
#define OO   64
#define JJ   33
#define C1c  4
#define F1c  16
#define C2c  32
#define NCLS 10
#define BN_EPS 1e-5f

// ---------------- scratch ----------------
__device__ float g_C[NN * JJ * FF];
__device__ float g_Wt[FF * OO];              // W1 transposed [k][o]
__device__ float g_O1[NN * JJ * OO];
__device__ float g_Xrow[NN * OO];
__device__ float g_X2[NN * C2c];
__device__ int   g_ipm[NN * FF];
__device__ int   g_ms[NN * FF];
__device__ float g_sgn[NN * FF];
__device__ int   g_cnt2[1];

__device__ __forceinline__ unsigned long long pk2(float lo, float hi) {
    unsigned long long r;
    asm("mov.b64 %0, {%1, %2};" : "=l"(r) : "f"(lo), "f"(hi));
    return r;
}
__device__ __forceinline__ void upk2(unsigned long long v, float& lo, float& hi) {
    asm("mov.b64 {%0, %1}, %2;" : "=f"(lo), "=f"(hi) : "l"(v));
}
__device__ __forceinline__ unsigned long long ffma2(unsigned long long a,
                                                    unsigned long long b,
                                                    unsigned long long c) {
    unsigned long long d;
    asm("fma.rn.f32x2 %0, %1, %2, %3;" : "=l"(d) : "l"(a), "l"(b), "l"(c));
    return d;
}

// ============================================================================
// K1: per-node hybrid bitonic sort of r = s/x (+ one-time W1 transpose).
// grid=64, block=1024.
// ============================================================================
__global__ void k_sort(const float* __restrict__ x, const float* __restrict__ nb,
                       const float* __restrict__ W1)
{
    int n = blockIdx.x, t = threadIdx.x;
    __shared__ float sk[FF];
    __shared__ int   sp[FF];

    if (n == 0 && t == 0) g_cnt2[0] = 0;
    // W1 transpose sidecar: CTA n covers k-rows n*16 .. n*16+15
    if (t < 1024) {
        int kr = n * 16 + (t >> 6), o = t & 63;
        g_Wt[kr * 64 + o] = W1[o * FF + kr];
    }

    float xv = x[(size_t)n * FF + t];
    const float* nbb = nb + (size_t)n * KK * FF;
    float s = 0.f;
    #pragma unroll
    for (int k = 0; k < KK; k++) s += nbb[k * FF + t];

    float key = s / xv;
    int   pay = t;
    float myr = key;
    g_sgn[(size_t)n * FF + t] = (xv >= 0.f) ? 1.f : -1.f;

    #pragma unroll
    for (int k = 2; k <= 32; k <<= 1) {
        #pragma unroll
        for (int j = k >> 1; j >= 1; j >>= 1) {
            float ok = __shfl_xor_sync(0xffffffffu, key, j);
            int   op = __shfl_xor_sync(0xffffffffu, pay, j);
            bool keepmin = (((t & k) == 0) == ((t & j) == 0));
            bool take = keepmin ? (ok < key) : (ok > key);
            if (take) { key = ok; pay = op; }
        }
    }
    for (int k = 64; k <= FF; k <<= 1) {
        for (int j = k >> 1; j >= 32; j >>= 1) {
            sk[t] = key; sp[t] = pay;
            __syncthreads();
            float ok = sk[t ^ j]; int op = sp[t ^ j];
            bool keepmin = (((t & k) == 0) == ((t & j) == 0));
            bool take = keepmin ? (ok < key) : (ok > key);
            if (take) { key = ok; pay = op; }
            __syncthreads();
        }
        #pragma unroll
        for (int j = 16; j >= 1; j >>= 1) {
            float ok = __shfl_xor_sync(0xffffffffu, key, j);
            int   op = __shfl_xor_sync(0xffffffffu, pay, j);
            bool keepmin = (((t & k) == 0) == ((t & j) == 0));
            bool take = keepmin ? (ok < key) : (ok > key);
            if (take) { key = ok; pay = op; }
        }
    }

    sk[t] = key;
    g_ipm[(size_t)n * FF + pay] = t;
    __syncthreads();

    float th = -myr;
    int lo = 0, hi = FF;
    #pragma unroll
    for (int it = 0; it < 10; it++) {
        int mid = (lo + hi) >> 1;
        if (sk[mid] < th) lo = mid + 1; else hi = mid;
    }
    g_ms[(size_t)n * FF + t] = lo;
}

// ============================================================================
// K2: per-(n,j) column scan + threshold lookup. grid=(33,64), block=1024.
// ============================================================================
__global__ void k_cols(const float* __restrict__ x, const float* __restrict__ nb)
{
    int j = blockIdx.x, n = blockIdx.y, t = threadIdx.x;
    __shared__ float sc[FF];
    __shared__ float ws[32];

    const float* col = (j == 0) ? (x + (size_t)n * FF)
                                : (nb + ((size_t)n * KK + (j - 1)) * FF);
    int   ip = g_ipm[(size_t)n * FF + t];
    int   m  = g_ms[(size_t)n * FF + t];
    float sg = g_sgn[(size_t)n * FF + t];
    float v  = col[t] * sg;
    sc[ip] = v;
    __syncthreads();

    float val = sc[t];
    int lane = t & 31, wid = t >> 5;
    #pragma unroll
    for (int d = 1; d < 32; d <<= 1) {
        float o = __shfl_up_sync(0xffffffffu, val, d);
        if (lane >= d) val += o;
    }
    if (lane == 31) ws[wid] = val;
    __syncthreads();
    if (wid == 0) {
        float wv = ws[lane];
        #pragma unroll
        for (int d = 1; d < 32; d <<= 1) {
            float o = __shfl_up_sync(0xffffffffu, wv, d);
            if (lane >= d) wv += o;
        }
        ws[lane] = wv;
    }
    __syncthreads();
    float off = wid ? ws[wid - 1] : 0.f;
    sc[t] = val + off;
    __syncthreads();

    float T = sc[FF - 1];
    float P = m ? sc[m - 1] : 0.f;
    g_C[((size_t)n * JJ + j) * FF + t] = sg * (T - 2.f * P);
}

// ============================================================================
// K3: single-pass GEMM with f32x2 FMAs. grid=132 (m-tile 16), block=256.
// out1[m][o] = sum_k C[m][k] * Wt[k][o]
// ============================================================================
__global__ void __launch_bounds__(256, 1) k_gemm()
{
    __shared__ float Cs[16][64];
    __shared__ float Wt_s[64][68];
    int mt  = blockIdx.x;
    int m0  = mt * 16;
    int tid = threadIdx.x;
    int m   = tid >> 4;
    int o0  = (tid & 15) * 4;

    unsigned long long acc01 = pk2(0.f, 0.f), acc23 = pk2(0.f, 0.f);

    for (int kb = 0; kb < FF; kb += 64) {
        #pragma unroll
        for (int u = 0; u < 4; u++) {
            int e = u * 256 + tid;
            Cs[e >> 6][e & 63] = g_C[(size_t)(m0 + (e >> 6)) * FF + kb + (e & 63)];
        }
        #pragma unroll
        for (int u = 0; u < 16; u++) {
            int e = u * 256 + tid;
            Wt_s[e >> 6][e & 63] = g_Wt[(size_t)(kb + (e >> 6)) * 64 + (e & 63)];
        }
        __syncthreads();
        #pragma unroll
        for (int kc = 0; kc < 64; kc++) {
            float c = Cs[m][kc];
            unsigned long long c2 = pk2(c, c);
            ulonglong2 w = *(const ulonglong2*)&Wt_s[kc][o0];
            acc01 = ffma2(c2, w.x, acc01);
            acc23 = ffma2(c2, w.y, acc23);
        }
        __syncthreads();
    }

    float4 r;
    upk2(acc01, r.x, r.y);
    upk2(acc23, r.z, r.w);
    int mg = m0 + m;
    *(float4*)&g_O1[(size_t)mg * OO + o0] = r;
    if (mg % 33 == 0)
        *(float4*)&g_Xrow[(size_t)(mg / 33) * OO + o0] = r;
}

// ============================================================================
// K4: layer2 + fused final. grid=64, block=256.
// ============================================================================
__global__ void k_layer2(const float* __restrict__ W2,
                         const float* __restrict__ bn1w, const float* __restrict__ bn1b,
                         const float* __restrict__ bn2w, const float* __restrict__ bn2b,
                         const float* __restrict__ lw,  const float* __restrict__ lb,
                         float* __restrict__ out)
{
    int n = blockIdx.x, t = threadIdx.x;
    __shared__ float nbs[KK * 64];
    __shared__ float red[1024];
    __shared__ float tmp[16];
    __shared__ float x1s[64], t2s[64], xa2s[64];
    __shared__ float gm[4], gr[4], cm[4], cr[4];
    __shared__ int last;

    const float4* O1v = (const float4*)g_O1;
    const float4* Xv  = (const float4*)g_Xrow;
    float4* nbsv = (float4*)nbs;

    #pragma unroll
    for (int u = 0; u < 2; u++) {
        int i4 = u * 256 + t;
        int row = i4 >> 4, c4 = i4 & 15;
        nbsv[i4] = O1v[((size_t)(n * JJ + 1 + row)) * 16 + c4];
    }

    int ch = (t & 15) >> 2;
    float gs1 = 0.f, gs2 = 0.f;
    #pragma unroll
    for (int u = 0; u < 4; u++) {
        float4 q = Xv[u * 256 + t];
        gs1 += q.x + q.y + q.z + q.w;
        gs2 += q.x * q.x + q.y * q.y + q.z * q.z + q.w * q.w;
    }
    __syncthreads();

    float ns1 = 0.f, ns2 = 0.f;
    #pragma unroll
    for (int u = 0; u < 2; u++) {
        float4 q = nbsv[u * 256 + t];
        ns1 += q.x + q.y + q.z + q.w;
        ns2 += q.x * q.x + q.y * q.y + q.z * q.z + q.w * q.w;
    }
    int sic = ((t >> 4) << 2) | (t & 3);
    red[      ch * 64 + sic] = gs1;
    red[256 + ch * 64 + sic] = gs2;
    red[512 + ch * 64 + sic] = ns1;
    red[768 + ch * 64 + sic] = ns2;
    __syncthreads();

    {
        int arr = t >> 6, c = (t >> 4) & 3, l = t & 15;
        int base = arr * 256 + c * 64;
        float v = red[base + l] + red[base + l + 16] + red[base + l + 32] + red[base + l + 48];
        #pragma unroll
        for (int d = 8; d > 0; d >>= 1)
            v += __shfl_down_sync(0xffffffffu, v, d, 16);
        if (l == 0) tmp[arr * 4 + c] = v;
    }
    __syncthreads();
    if (t < 4) {
        float m = tmp[t] / 1024.f;
        gm[t] = m; gr[t] = rsqrtf(tmp[4 + t] / 1024.f - m * m + BN_EPS);
        float m2 = tmp[8 + t] / 512.f;
        cm[t] = m2; cr[t] = rsqrtf(tmp[12 + t] / 512.f - m2 * m2 + BN_EPS);
    }
    __syncthreads();

    if (t < 64) {
        float v = g_Xrow[n * OO + t];
        int c = t >> 4;
        float y = (v - gm[c]) * gr[c] * bn1w[c] + bn1b[c];
        x1s[t] = y / (1.f + fabsf(y));
    }
    #pragma unroll
    for (int u = 0; u < 2; u++) {
        int i4 = u * 256 + t;
        int c = ((i4 & 15) >> 2);
        float4 q = nbsv[i4];
        float sw = cr[c] * bn1w[c];
        float y;
        y = (q.x - cm[c]) * sw + bn1b[c]; q.x = y / (1.f + fabsf(y));
        y = (q.y - cm[c]) * sw + bn1b[c]; q.y = y / (1.f + fabsf(y));
        y = (q.z - cm[c]) * sw + bn1b[c]; q.z = y / (1.f + fabsf(y));
        y = (q.w - cm[c]) * sw + bn1b[c]; q.w = y / (1.f + fabsf(y));
        nbsv[i4] = q;
    }
    __syncthreads();
    if (t < 64) {
        float a = 0.f;
        #pragma unroll
        for (int k = 0; k < KK; k++) a += nbs[k * 64 + t];
        t2s[t] = a;
    }
    __syncthreads();

    {
        int ai = t >> 4, b = t & 15;
        float sgv[4], ctr[4];
        float den = 1e-7f;
        #pragma unroll
        for (int cc = 0; cc < 4; cc++) {
            float raw = x1s[cc * 16 + ai] * t2s[cc * 16 + b]
                      + x1s[cc * 16 + b]  * t2s[cc * 16 + ai];
            float mag = sqrtf(fmaxf(fabsf(raw), 1e-8f));
            float sg  = (raw > 0.f) ? mag : ((raw < 0.f) ? -mag : 0.f);
            sgv[cc] = sg;
            den += fabsf(sg);
        }
        float inv = 1.f / den;
        #pragma unroll
        for (int cc = 0; cc < 4; cc++)
            ctr[cc] = sgv[cc] * inv * x1s[cc * 16 + b];
        #pragma unroll
        for (int d = 8; d > 0; d >>= 1) {
            #pragma unroll
            for (int cc = 0; cc < 4; cc++)
                ctr[cc] += __shfl_down_sync(0xffffffffu, ctr[cc], d, 16);
        }
        if (b == 0) {
            #pragma unroll
            for (int cc = 0; cc < 4; cc++) xa2s[cc * 16 + ai] = ctr[cc];
        }
    }
    __syncthreads();

    {
        int o = t >> 3, seg = t & 7;
        float acc = 0.f;
        #pragma unroll
        for (int i = seg * 8; i < seg * 8 + 8; i++)
            acc += W2[o * 64 + i] * xa2s[i];
        #pragma unroll
        for (int d = 4; d > 0; d >>= 1)
            acc += __shfl_down_sync(0xffffffffu, acc, d, 8);
        if (seg == 0) g_X2[n * C2c + o] = acc;
    }

    __threadfence();
    __syncthreads();
    if (t == 0) last = (atomicAdd(&g_cnt2[0], 1) == NN - 1);
    __syncthreads();
    if (!last) return;
    __threadfence();

    float* z = nbs;
    for (int i = t; i < NN * C2c; i += 256) z[i] = g_X2[i];
    __syncthreads();

    {
        int q = t & 31, g = t >> 5;
        float s1 = 0.f, s2 = 0.f;
        #pragma unroll
        for (int nn = g * 8; nn < g * 8 + 8; nn++) {
            float v = z[nn * C2c + q];
            s1 += v; s2 += v * v;
        }
        red[q * 8 + g] = s1; red[256 + q * 8 + g] = s2;
    }
    __syncthreads();
    __shared__ float qm[C2c], qr[C2c];
    if (t < C2c) {
        float s1 = 0.f, s2 = 0.f;
        #pragma unroll
        for (int g = 0; g < 8; g++) { s1 += red[t * 8 + g]; s2 += red[256 + t * 8 + g]; }
        float m = s1 / 64.f;
        qm[t] = m; qr[t] = rsqrtf(s2 / 64.f - m * m + BN_EPS);
    }
    __syncthreads();
    for (int i = t; i < NN * C2c; i += 256) {
        int q = i & 31;
        float y = (z[i] - qm[q]) * qr[q] * bn2w[q] + bn2b[q];
        z[i] = y / (1.f + fabsf(y));
    }
    __syncthreads();
    for (int i = t; i < NN * NCLS; i += 256) {
        int nn = i / NCLS, cls = i - nn * NCLS;
        float acc = lb[cls];
        #pragma unroll
        for (int q = 0; q < C2c; q++) acc += z[nn * C2c + q] * lw[cls * C2c + q];
        out[i] = acc;
    }
}

// ============================================================================
extern "C" void kernel_launch(void* const* d_in, const int* in_sizes, int n_in,
                              void* d_out, int out_size)
{
    const float* x    = (const float*)d_in[0];
    const float* nb   = (const float*)d_in[1];
    const float* W1   = (const float*)d_in[2];
    const float* W2   = (const float*)d_in[3];
    const float* bn1w = (const float*)d_in[4];
    const float* bn1b = (const float*)d_in[5];
    const float* bn2w = (const float*)d_in[6];
    const float* bn2b = (const float*)d_in[7];
    const float* lw   = (const float*)d_in[8];
    const float* lb   = (const float*)d_in[9];
    float* out = (float*)d_out;

    k_sort<<<NN, 1024>>>(x, nb, W1);
    dim3 gc(JJ, NN);
    k_cols<<<gc, 1024>>>(x, nb);
    k_gemm<<<132, 256>>>();
    k_layer2<<<NN, 256>>>(W2, bn1w, bn1b, bn2w, bn2b, lw, lb, out);
}

// round 6
// speedup vs baseline: 1.0979x; 1.0293x over previous
#include <cuda_runtime.h>
#include <math.h>

#define NN   64
#define KK   32
#define FF   1024
#define OO   64
#define JJ   33
#define C2c  32
#define NCLS 10
#define BN_EPS 1e-5f

typedef unsigned long long ull;

// ---------------- scratch ----------------
__device__ float g_C[NN * JJ * FF];
__device__ float g_part[8 * NN * JJ * OO];
__device__ float g_Xrow[NN * OO];
__device__ float g_X2[NN * C2c];
__device__ int   g_ipm[NN * FF];
__device__ int   g_ms[NN * FF];
__device__ float g_sgn[NN * FF];
__device__ int   g_cnt[64];
__device__ int   g_done[1];
__device__ int   g_cnt2[1];

__device__ __forceinline__ ull pk2(float lo, float hi) {
    ull r; asm("mov.b64 %0, {%1, %2};" : "=l"(r) : "f"(lo), "f"(hi)); return r;
}
__device__ __forceinline__ void upk2(ull v, float& lo, float& hi) {
    asm("mov.b64 {%0, %1}, %2;" : "=f"(lo), "=f"(hi) : "l"(v));
}
__device__ __forceinline__ ull ffma2(ull a, ull b, ull c) {
    ull d; asm("fma.rn.f32x2 %0, %1, %2, %3;" : "=l"(d) : "l"(a), "l"(b), "l"(c)); return d;
}

// ============================================================================
// K1: per-node hybrid bitonic sort of r = s/x. grid=64, block=1024.
// ============================================================================
__global__ void k_sort(const float* __restrict__ x, const float* __restrict__ nb)
{
    int n = blockIdx.x, t = threadIdx.x;
    __shared__ float sk[FF];
    __shared__ int   sp[FF];

    if (n == 0 && t < 64) g_cnt[t] = 0;
    if (n == 0 && t == 64) g_cnt2[0] = 0;
    if (n == 0 && t == 65) g_done[0] = 0;

    float xv = x[(size_t)n * FF + t];
    const float* nbb = nb + (size_t)n * KK * FF;
    float s = 0.f;
    #pragma unroll
    for (int k = 0; k < KK; k++) s += nbb[k * FF + t];

    float key = s / xv;
    int   pay = t;
    float myr = key;
    g_sgn[(size_t)n * FF + t] = (xv >= 0.f) ? 1.f : -1.f;

    #pragma unroll
    for (int k = 2; k <= 32; k <<= 1) {
        #pragma unroll
        for (int j = k >> 1; j >= 1; j >>= 1) {
            float ok = __shfl_xor_sync(0xffffffffu, key, j);
            int   op = __shfl_xor_sync(0xffffffffu, pay, j);
            bool keepmin = (((t & k) == 0) == ((t & j) == 0));
            bool take = keepmin ? (ok < key) : (ok > key);
            if (take) { key = ok; pay = op; }
        }
    }
    for (int k = 64; k <= FF; k <<= 1) {
        for (int j = k >> 1; j >= 32; j >>= 1) {
            sk[t] = key; sp[t] = pay;
            __syncthreads();
            float ok = sk[t ^ j]; int op = sp[t ^ j];
            bool keepmin = (((t & k) == 0) == ((t & j) == 0));
            bool take = keepmin ? (ok < key) : (ok > key);
            if (take) { key = ok; pay = op; }
            __syncthreads();
        }
        #pragma unroll
        for (int j = 16; j >= 1; j >>= 1) {
            float ok = __shfl_xor_sync(0xffffffffu, key, j);
            int   op = __shfl_xor_sync(0xffffffffu, pay, j);
            bool keepmin = (((t & k) == 0) == ((t & j) == 0));
            bool take = keepmin ? (ok < key) : (ok > key);
            if (take) { key = ok; pay = op; }
        }
    }

    sk[t] = key;
    g_ipm[(size_t)n * FF + pay] = t;
    __syncthreads();

    float th = -myr;
    int lo = 0, hi = FF;
    #pragma unroll
    for (int it = 0; it < 10; it++) {
        int mid = (lo + hi) >> 1;
        if (sk[mid] < th) lo = mid + 1; else hi = mid;
    }
    g_ms[(size_t)n * FF + t] = lo;
}

// ============================================================================
// K2: per-(n,j) column scan + threshold lookup. grid=(33,64), block=1024.
// ============================================================================
__global__ void k_cols(const float* __restrict__ x, const float* __restrict__ nb)
{
    int j = blockIdx.x, n = blockIdx.y, t = threadIdx.x;
    __shared__ float sc[FF];
    __shared__ float ws[32];

    const float* col = (j == 0) ? (x + (size_t)n * FF)
                                : (nb + ((size_t)n * KK + (j - 1)) * FF);
    int   ip = g_ipm[(size_t)n * FF + t];
    int   m  = g_ms[(size_t)n * FF + t];
    float sg = g_sgn[(size_t)n * FF + t];
    float v  = col[t] * sg;
    sc[ip] = v;
    __syncthreads();

    float val = sc[t];
    int lane = t & 31, wid = t >> 5;
    #pragma unroll
    for (int d = 1; d < 32; d <<= 1) {
        float o = __shfl_up_sync(0xffffffffu, val, d);
        if (lane >= d) val += o;
    }
    if (lane == 31) ws[wid] = val;
    __syncthreads();
    if (wid == 0) {
        float wv = ws[lane];
        #pragma unroll
        for (int d = 1; d < 32; d <<= 1) {
            float o = __shfl_up_sync(0xffffffffu, wv, d);
            if (lane >= d) wv += o;
        }
        ws[lane] = wv;
    }
    __syncthreads();
    float off = wid ? ws[wid - 1] : 0.f;
    sc[t] = val + off;
    __syncthreads();

    float T = sc[FF - 1];
    float P = m ? sc[m - 1] : 0.f;
    g_C[((size_t)n * JJ + j) * FF + t] = sg * (T - 2.f * P);
}

// ============================================================================
// K3: fused node-GEMM (split-K 8, FFMA2) + layer2 + final. grid=(64,8), block=256.
// ============================================================================
__global__ void __launch_bounds__(256) k_fused(
                         const float* __restrict__ W1,
                         const float* __restrict__ W2,
                         const float* __restrict__ bn1w, const float* __restrict__ bn1b,
                         const float* __restrict__ bn2w, const float* __restrict__ bn2b,
                         const float* __restrict__ lw,  const float* __restrict__ lb,
                         float* __restrict__ out)
{
    int n  = blockIdx.x;           // node
    int ks = blockIdx.y;           // k-split
    int t  = threadIdx.x;

    __shared__ float U[3456];      // union buffer
    float* Cs = U;                 // gemm: [33][33]
    float* Wt = U + 1120;          // gemm: [32][68]
    float* nbsh = U;               // layer2: [32][64]
    float* xr = U + 2048;          // layer2: x row [64]
    float* red = U + 2112;         // layer2: reduction [1024]
    __shared__ float x1s[64], t2s[64], xa2s[64];
    __shared__ float gm[4], gr[4], cm[4], cr[4], tmp[16];
    __shared__ float qm[C2c], qr[C2c];
    __shared__ int last;

    int mg = t >> 4;               // 0..15 -> m = 2mg, 2mg+1 (+ m=32 for mg==15)
    int og = t & 15;               // o = og*4 .. og*4+3
    int m0 = 2 * mg, m1 = m0 + 1;
    bool xtra = (mg == 15);

    ull a01 = pk2(0.f, 0.f), a23 = a01, b01 = a01, b23 = a01, e01 = a01, e23 = a01;

    for (int kb4 = 0; kb4 < 4; kb4++) {
        int kb = ks * 128 + kb4 * 32;
        for (int e = t; e < 1056; e += 256) {
            int ri = e >> 5, kc = e & 31;
            Cs[ri * 33 + kc] = g_C[((size_t)n * JJ + ri) * FF + kb + kc];
        }
        #pragma unroll
        for (int u = 0; u < 8; u++) {
            int e = u * 256 + t;
            int o = e >> 5, kc = e & 31;
            Wt[kc * 68 + o] = W1[(size_t)o * FF + kb + kc];
        }
        __syncthreads();
        #pragma unroll
        for (int kc = 0; kc < 32; kc++) {
            float c0 = Cs[m0 * 33 + kc], c1 = Cs[m1 * 33 + kc];
            ull c0p = pk2(c0, c0), c1p = pk2(c1, c1);
            ulonglong2 w = *(const ulonglong2*)&Wt[kc * 68 + og * 4];
            a01 = ffma2(c0p, w.x, a01); a23 = ffma2(c0p, w.y, a23);
            b01 = ffma2(c1p, w.x, b01); b23 = ffma2(c1p, w.y, b23);
            if (xtra) {
                float c2 = Cs[32 * 33 + kc];
                ull c2p = pk2(c2, c2);
                e01 = ffma2(c2p, w.x, e01); e23 = ffma2(c2p, w.y, e23);
            }
        }
        __syncthreads();
    }

    {
        size_t base = (size_t)ks * (NN * JJ * OO) + (size_t)n * (JJ * OO);
        float4 r;
        upk2(a01, r.x, r.y); upk2(a23, r.z, r.w);
        *(float4*)&g_part[base + m0 * 64 + og * 4] = r;
        upk2(b01, r.x, r.y); upk2(b23, r.z, r.w);
        *(float4*)&g_part[base + m1 * 64 + og * 4] = r;
        if (xtra) {
            upk2(e01, r.x, r.y); upk2(e23, r.z, r.w);
            *(float4*)&g_part[base + 32 * 64 + og * 4] = r;
        }
    }

    __threadfence();
    __syncthreads();
    if (t == 0) last = (atomicAdd(&g_cnt[n], 1) == 7);
    __syncthreads();
    if (!last) return;
    __threadfence();

    // ---- split-K reduce into SMEM (+ x-row sidecar to global) ----
    {
        const float4* ps = (const float4*)g_part;
        float4* nb4 = (float4*)nbsh;
        float4* xr4 = (float4*)xr;
        float4* gx4 = (float4*)g_Xrow;
        for (int i4 = t; i4 < 528; i4 += 256) {
            float4 a = make_float4(0.f, 0.f, 0.f, 0.f);
            #pragma unroll
            for (int s = 0; s < 8; s++) {
                float4 p = ps[(size_t)s * (NN * 528) + n * 528 + i4];
                a.x += p.x; a.y += p.y; a.z += p.z; a.w += p.w;
            }
            int m = i4 >> 4, off = i4 & 15;
            if (m == 0) { xr4[off] = a; gx4[n * 16 + off] = a; }
            else        nb4[(m - 1) * 16 + off] = a;
        }
    }
    __threadfence();
    __syncthreads();
    if (t == 0) {
        atomicAdd(&g_done[0], 1);
        while (atomicAdd(&g_done[0], 0) < NN) __nanosleep(64);
    }
    __syncthreads();

    // ---- layer 2 ----
    const float4* Xv = (const float4*)g_Xrow;
    float4* nbsv = (float4*)nbsh;

    int ch = (t & 15) >> 2;
    float gs1 = 0.f, gs2 = 0.f;
    #pragma unroll
    for (int u = 0; u < 4; u++) {
        float4 q = __ldcg(&Xv[u * 256 + t]);
        gs1 += q.x + q.y + q.z + q.w;
        gs2 += q.x * q.x + q.y * q.y + q.z * q.z + q.w * q.w;
    }
    float ns1 = 0.f, ns2 = 0.f;
    #pragma unroll
    for (int u = 0; u < 2; u++) {
        float4 q = nbsv[u * 256 + t];
        ns1 += q.x + q.y + q.z + q.w;
        ns2 += q.x * q.x + q.y * q.y + q.z * q.z + q.w * q.w;
    }
    int sic = ((t >> 4) << 2) | (t & 3);
    red[      ch * 64 + sic] = gs1;
    red[256 + ch * 64 + sic] = gs2;
    red[512 + ch * 64 + sic] = ns1;
    red[768 + ch * 64 + sic] = ns2;
    __syncthreads();
    {
        int arr = t >> 6, c = (t >> 4) & 3, l = t & 15;
        int base = arr * 256 + c * 64;
        float v = red[base + l] + red[base + l + 16] + red[base + l + 32] + red[base + l + 48];
        #pragma unroll
        for (int d = 8; d > 0; d >>= 1)
            v += __shfl_down_sync(0xffffffffu, v, d, 16);
        if (l == 0) tmp[arr * 4 + c] = v;
    }
    __syncthreads();
    if (t < 4) {
        float m = tmp[t] / 1024.f;
        gm[t] = m; gr[t] = rsqrtf(tmp[4 + t] / 1024.f - m * m + BN_EPS);
        float m2 = tmp[8 + t] / 512.f;
        cm[t] = m2; cr[t] = rsqrtf(tmp[12 + t] / 512.f - m2 * m2 + BN_EPS);
    }
    __syncthreads();

    if (t < 64) {
        float v = xr[t];
        int c = t >> 4;
        float y = (v - gm[c]) * gr[c] * bn1w[c] + bn1b[c];
        x1s[t] = y / (1.f + fabsf(y));
    }
    #pragma unroll
    for (int u = 0; u < 2; u++) {
        int i4 = u * 256 + t;
        int c = ((i4 & 15) >> 2);
        float4 q = nbsv[i4];
        float sw = cr[c] * bn1w[c];
        float y;
        y = (q.x - cm[c]) * sw + bn1b[c]; q.x = y / (1.f + fabsf(y));
        y = (q.y - cm[c]) * sw + bn1b[c]; q.y = y / (1.f + fabsf(y));
        y = (q.z - cm[c]) * sw + bn1b[c]; q.z = y / (1.f + fabsf(y));
        y = (q.w - cm[c]) * sw + bn1b[c]; q.w = y / (1.f + fabsf(y));
        nbsv[i4] = q;
    }
    __syncthreads();
    if (t < 64) {
        float a = 0.f;
        #pragma unroll
        for (int k = 0; k < KK; k++) a += nbsh[k * 64 + t];
        t2s[t] = a;
    }
    __syncthreads();

    {   // xa2s: one (ai,b) pair per thread
        int ai = t >> 4, b = t & 15;
        float sgv[4], ctr[4];
        float den = 1e-7f;
        #pragma unroll
        for (int cc = 0; cc < 4; cc++) {
            float raw = x1s[cc * 16 + ai] * t2s[cc * 16 + b]
                      + x1s[cc * 16 + b]  * t2s[cc * 16 + ai];
            float mag = sqrtf(fmaxf(fabsf(raw), 1e-8f));
            float sg  = (raw > 0.f) ? mag : ((raw < 0.f) ? -mag : 0.f);
            sgv[cc] = sg;
            den += fabsf(sg);
        }
        float inv = 1.f / den;
        #pragma unroll
        for (int cc = 0; cc < 4; cc++)
            ctr[cc] = sgv[cc] * inv * x1s[cc * 16 + b];
        #pragma unroll
        for (int d = 8; d > 0; d >>= 1) {
            #pragma unroll
            for (int cc = 0; cc < 4; cc++)
                ctr[cc] += __shfl_down_sync(0xffffffffu, ctr[cc], d, 16);
        }
        if (b == 0) {
            #pragma unroll
            for (int cc = 0; cc < 4; cc++) xa2s[cc * 16 + ai] = ctr[cc];
        }
    }
    __syncthreads();

    {   // W2 matvec
        int o = t >> 3, seg = t & 7;
        float acc = 0.f;
        #pragma unroll
        for (int i = seg * 8; i < seg * 8 + 8; i++)
            acc += W2[o * 64 + i] * xa2s[i];
        #pragma unroll
        for (int d = 4; d > 0; d >>= 1)
            acc += __shfl_down_sync(0xffffffffu, acc, d, 8);
        if (seg == 0) g_X2[n * C2c + o] = acc;
    }

    __threadfence();
    __syncthreads();
    if (t == 0) last = (atomicAdd(&g_cnt2[0], 1) == NN - 1);
    __syncthreads();
    if (!last) return;
    __threadfence();

    // ---- final: BN2 + softsign + linear ----
    float* z = nbsh;
    for (int i = t; i < NN * C2c; i += 256) z[i] = __ldcg(&g_X2[i]);
    __syncthreads();
    {
        int q = t & 31, g = t >> 5;
        float s1 = 0.f, s2 = 0.f;
        #pragma unroll
        for (int nn = g * 8; nn < g * 8 + 8; nn++) {
            float v = z[nn * C2c + q];
            s1 += v; s2 += v * v;
        }
        red[q * 8 + g] = s1; red[256 + q * 8 + g] = s2;
    }
    __syncthreads();
    if (t < C2c) {
        float s1 = 0.f, s2 = 0.f;
        #pragma unroll
        for (int g = 0; g < 8; g++) { s1 += red[t * 8 + g]; s2 += red[256 + t * 8 + g]; }
        float m = s1 / 64.f;
        qm[t] = m; qr[t] = rsqrtf(s2 / 64.f - m * m + BN_EPS);
    }
    __syncthreads();
    for (int i = t; i < NN * C2c; i += 256) {
        int q = i & 31;
        float y = (z[i] - qm[q]) * qr[q] * bn2w[q] + bn2b[q];
        z[i] = y / (1.f + fabsf(y));
    }
    __syncthreads();
    for (int i = t; i < NN * NCLS; i += 256) {
        int nn = i / NCLS, cls = i - nn * NCLS;
        float acc = lb[cls];
        #pragma unroll
        for (int q = 0; q < C2c; q++) acc += z[nn * C2c + q] * lw[cls * C2c + q];
        out[i] = acc;
    }
}

// ============================================================================
extern "C" void kernel_launch(void* const* d_in, const int* in_sizes, int n_in,
                              void* d_out, int out_size)
{
    const float* x    = (const float*)d_in[0];
    const float* nb   = (const float*)d_in[1];
    const float* W1   = (const float*)d_in[2];
    const float* W2   = (const float*)d_in[3];
    const float* bn1w = (const float*)d_in[4];
    const float* bn1b = (const float*)d_in[5];
    const float* bn2w = (const float*)d_in[6];
    const float* bn2b = (const float*)d_in[7];
    const float* lw   = (const float*)d_in[8];
    const float* lb   = (const float*)d_in[9];
    float* out = (float*)d_out;

    k_sort<<<NN, 1024>>>(x, nb);
    dim3 gc(JJ, NN);
    k_cols<<<gc, 1024>>>(x, nb);
    dim3 gf(NN, 8);
    k_fused<<<gf, 256>>>(W1, W2, bn1w, bn1b, bn2w, bn2b, lw, lb, out);
}

// round 7
// speedup vs baseline: 1.3871x; 1.2634x over previous
#include <cuda_runtime.h>
#include <math.h>

#define NN   64
#define KK   32
#define FF   1024
#define OO   64
#define JJ   33
#define C2c  32
#define NCLS 10
#define BN_EPS 1e-5f

typedef unsigned long long ull;
typedef unsigned int uint;

// ---------------- scratch ----------------
__device__ float g_C[NN * JJ * FF];
__device__ float g_part[8 * NN * JJ * OO];
__device__ float g_O1[NN * JJ * OO];
__device__ float g_Xrow[NN * OO];
__device__ float g_X2[NN * C2c];
__device__ uint  g_aux[NN * FF];             // packed: ip(10) | m(11)<<10 | neg<<21
__device__ int   g_cnt[64];
__device__ int   g_cnt2[1];

__device__ __forceinline__ ull pk2(float lo, float hi) {
    ull r; asm("mov.b64 %0, {%1, %2};" : "=l"(r) : "f"(lo), "f"(hi)); return r;
}
__device__ __forceinline__ void upk2(ull v, float& lo, float& hi) {
    asm("mov.b64 {%0, %1}, %2;" : "=f"(lo), "=f"(hi) : "l"(v));
}
__device__ __forceinline__ ull ffma2(ull a, ull b, ull c) {
    ull d; asm("fma.rn.f32x2 %0, %1, %2, %3;" : "=l"(d) : "l"(a), "l"(b), "l"(c)); return d;
}

// ============================================================================
// K1: per-node hybrid bitonic sort of r = s/x. grid=64, block=1024.
// ============================================================================
__global__ void k_sort(const float* __restrict__ x, const float* __restrict__ nb)
{
    int n = blockIdx.x, t = threadIdx.x;
    __shared__ float sk[FF];
    __shared__ int   sp[FF];

    if (n == 0 && t < 64) g_cnt[t] = 0;
    if (n == 0 && t == 64) g_cnt2[0] = 0;

    float xv = x[(size_t)n * FF + t];
    const float* nbb = nb + (size_t)n * KK * FF;
    float s = 0.f;
    #pragma unroll
    for (int k = 0; k < KK; k++) s += nbb[k * FF + t];

    float key = s / xv;
    int   pay = t;
    float myr = key;

    #pragma unroll
    for (int k = 2; k <= 32; k <<= 1) {
        #pragma unroll
        for (int j = k >> 1; j >= 1; j >>= 1) {
            float ok = __shfl_xor_sync(0xffffffffu, key, j);
            int   op = __shfl_xor_sync(0xffffffffu, pay, j);
            bool keepmin = (((t & k) == 0) == ((t & j) == 0));
            bool take = keepmin ? (ok < key) : (ok > key);
            if (take) { key = ok; pay = op; }
        }
    }
    for (int k = 64; k <= FF; k <<= 1) {
        for (int j = k >> 1; j >= 32; j >>= 1) {
            sk[t] = key; sp[t] = pay;
            __syncthreads();
            float ok = sk[t ^ j]; int op = sp[t ^ j];
            bool keepmin = (((t & k) == 0) == ((t & j) == 0));
            bool take = keepmin ? (ok < key) : (ok > key);
            if (take) { key = ok; pay = op; }
            __syncthreads();
        }
        #pragma unroll
        for (int j = 16; j >= 1; j >>= 1) {
            float ok = __shfl_xor_sync(0xffffffffu, key, j);
            int   op = __shfl_xor_sync(0xffffffffu, pay, j);
            bool keepmin = (((t & k) == 0) == ((t & j) == 0));
            bool take = keepmin ? (ok < key) : (ok > key);
            if (take) { key = ok; pay = op; }
        }
    }

    sk[t] = key;               // sorted keys
    sp[pay] = t;               // inverse permutation: sp[orig] = sorted pos
    __syncthreads();

    float th = -myr;
    int lo = 0, hi = FF;
    #pragma unroll
    for (int it = 0; it < 10; it++) {
        int mid = (lo + hi) >> 1;
        if (sk[mid] < th) lo = mid + 1; else hi = mid;
    }
    uint pk = (uint)sp[t] | ((uint)lo << 10) | ((xv >= 0.f) ? 0u : (1u << 21));
    g_aux[(size_t)n * FF + t] = pk;
}

// ============================================================================
// K2: per-(n,j) column scan + threshold lookup. grid=(33,64), block=1024.
// ============================================================================
__global__ void k_cols(const float* __restrict__ x, const float* __restrict__ nb)
{
    int j = blockIdx.x, n = blockIdx.y, t = threadIdx.x;
    __shared__ float sc[FF];
    __shared__ float ws[32];

    const float* col = (j == 0) ? (x + (size_t)n * FF)
                                : (nb + ((size_t)n * KK + (j - 1)) * FF);
    uint  pk = g_aux[(size_t)n * FF + t];
    int   ip = pk & 1023;
    int   m  = (pk >> 10) & 2047;
    float sg = (pk & (1u << 21)) ? -1.f : 1.f;
    float v  = col[t] * sg;
    sc[ip] = v;
    __syncthreads();

    float val = sc[t];
    int lane = t & 31, wid = t >> 5;
    #pragma unroll
    for (int d = 1; d < 32; d <<= 1) {
        float o = __shfl_up_sync(0xffffffffu, val, d);
        if (lane >= d) val += o;
    }
    if (lane == 31) ws[wid] = val;
    __syncthreads();
    if (wid == 0) {
        float wv = ws[lane];
        #pragma unroll
        for (int d = 1; d < 32; d <<= 1) {
            float o = __shfl_up_sync(0xffffffffu, wv, d);
            if (lane >= d) wv += o;
        }
        ws[lane] = wv;
    }
    __syncthreads();
    float off = wid ? ws[wid - 1] : 0.f;
    sc[t] = val + off;
    __syncthreads();

    float T = sc[FF - 1];
    float P = m ? sc[m - 1] : 0.f;
    g_C[((size_t)n * JJ + j) * FF + t] = sg * (T - 2.f * P);
}

// ============================================================================
// K3: GEMM (split-K 8, FFMA2, transposed tiles) + fused reduce. grid=(33,8), block=256.
// ============================================================================
__global__ void k_gemm(const float* __restrict__ W1)
{
    __shared__ float Cs[32 * 68];     // [kc][m]  (68-stride, 16B-aligned rows)
    __shared__ float Wt[32 * 68];     // [kc][o]
    __shared__ int last;
    int mt  = blockIdx.x;
    int ks  = blockIdx.y;
    int tid = threadIdx.x;
    int mg  = tid >> 4;               // m-group: m = mg*4..mg*4+3
    int og  = tid & 15;               // o-group: o = og*4..og*4+3

    ull acc01[4], acc23[4];
    #pragma unroll
    for (int i = 0; i < 4; i++) { acc01[i] = pk2(0.f, 0.f); acc23[i] = acc01[i]; }

    int kb0 = ks * (FF / 8);
    for (int kb = kb0; kb < kb0 + (FF / 8); kb += 32) {
        #pragma unroll
        for (int u = 0; u < 8; u++) {
            int e = u * 256 + tid;
            int ri = e >> 5, kc = e & 31;
            Cs[kc * 68 + ri] = g_C[(size_t)(mt * 64 + ri) * FF + kb + kc];
        }
        #pragma unroll
        for (int u = 0; u < 8; u++) {
            int e = u * 256 + tid;
            int o = e >> 5, kc = e & 31;
            Wt[kc * 68 + o] = W1[(size_t)o * FF + kb + kc];
        }
        __syncthreads();
        #pragma unroll
        for (int kc = 0; kc < 32; kc++) {
            float4 cv = *(const float4*)&Cs[kc * 68 + mg * 4];
            ulonglong2 wv = *(const ulonglong2*)&Wt[kc * 68 + og * 4];
            ull cp;
            cp = pk2(cv.x, cv.x);
            acc01[0] = ffma2(cp, wv.x, acc01[0]); acc23[0] = ffma2(cp, wv.y, acc23[0]);
            cp = pk2(cv.y, cv.y);
            acc01[1] = ffma2(cp, wv.x, acc01[1]); acc23[1] = ffma2(cp, wv.y, acc23[1]);
            cp = pk2(cv.z, cv.z);
            acc01[2] = ffma2(cp, wv.x, acc01[2]); acc23[2] = ffma2(cp, wv.y, acc23[2]);
            cp = pk2(cv.w, cv.w);
            acc01[3] = ffma2(cp, wv.x, acc01[3]); acc23[3] = ffma2(cp, wv.y, acc23[3]);
        }
        __syncthreads();
    }
    float* pb = g_part + (size_t)ks * (NN * JJ * OO) + (size_t)mt * 64 * OO;
    #pragma unroll
    for (int i = 0; i < 4; i++) {
        float4 r;
        upk2(acc01[i], r.x, r.y);
        upk2(acc23[i], r.z, r.w);
        *(float4*)&pb[(mg * 4 + i) * OO + og * 4] = r;
    }

    __threadfence();
    __syncthreads();
    if (tid == 0) last = (atomicAdd(&g_cnt[mt], 1) == 7);
    __syncthreads();
    if (last) {
        __threadfence();
        const float4* ps = (const float4*)g_part;
        float4* po = (float4*)g_O1;
        float4* px = (float4*)g_Xrow;
        for (int i = tid; i < 1024; i += 256) {
            float4 a = make_float4(0.f, 0.f, 0.f, 0.f);
            #pragma unroll
            for (int s = 0; s < 8; s++) {
                float4 p = ps[(size_t)s * (NN * JJ * OO / 4) + mt * 1024 + i];
                a.x += p.x; a.y += p.y; a.z += p.z; a.w += p.w;
            }
            po[mt * 1024 + i] = a;
            int m = mt * 64 + (i >> 4);
            if (m % 33 == 0) px[(m / 33) * 16 + (i & 15)] = a;
        }
    }
}

// ============================================================================
// K4: layer2 + fused final. grid=64, block=256.  (R3-proven version)
// ============================================================================
__global__ void k_layer2(const float* __restrict__ W2,
                         const float* __restrict__ bn1w, const float* __restrict__ bn1b,
                         const float* __restrict__ bn2w, const float* __restrict__ bn2b,
                         const float* __restrict__ lw,  const float* __restrict__ lb,
                         float* __restrict__ out)
{
    int n = blockIdx.x, t = threadIdx.x;
    __shared__ float nbs[KK * 64];
    __shared__ float red[1024];
    __shared__ float tmp[16];
    __shared__ float x1s[64], t2s[64], xa2s[64];
    __shared__ float gm[4], gr[4], cm[4], cr[4];
    __shared__ int last;

    const float4* O1v = (const float4*)g_O1;
    const float4* Xv  = (const float4*)g_Xrow;
    float4* nbsv = (float4*)nbs;

    #pragma unroll
    for (int u = 0; u < 2; u++) {
        int i4 = u * 256 + t;
        int row = i4 >> 4, c4 = i4 & 15;
        nbsv[i4] = O1v[((size_t)(n * JJ + 1 + row)) * 16 + c4];
    }

    int ch = (t & 15) >> 2;
    float gs1 = 0.f, gs2 = 0.f;
    #pragma unroll
    for (int u = 0; u < 4; u++) {
        float4 q = Xv[u * 256 + t];
        gs1 += q.x + q.y + q.z + q.w;
        gs2 += q.x * q.x + q.y * q.y + q.z * q.z + q.w * q.w;
    }
    __syncthreads();

    float ns1 = 0.f, ns2 = 0.f;
    #pragma unroll
    for (int u = 0; u < 2; u++) {
        float4 q = nbsv[u * 256 + t];
        ns1 += q.x + q.y + q.z + q.w;
        ns2 += q.x * q.x + q.y * q.y + q.z * q.z + q.w * q.w;
    }
    int sic = ((t >> 4) << 2) | (t & 3);
    red[      ch * 64 + sic] = gs1;
    red[256 + ch * 64 + sic] = gs2;
    red[512 + ch * 64 + sic] = ns1;
    red[768 + ch * 64 + sic] = ns2;
    __syncthreads();

    {
        int arr = t >> 6, c = (t >> 4) & 3, l = t & 15;
        int base = arr * 256 + c * 64;
        float v = red[base + l] + red[base + l + 16] + red[base + l + 32] + red[base + l + 48];
        #pragma unroll
        for (int d = 8; d > 0; d >>= 1)
            v += __shfl_down_sync(0xffffffffu, v, d, 16);
        if (l == 0) tmp[arr * 4 + c] = v;
    }
    __syncthreads();
    if (t < 4) {
        float m = tmp[t] / 1024.f;
        gm[t] = m; gr[t] = rsqrtf(tmp[4 + t] / 1024.f - m * m + BN_EPS);
        float m2 = tmp[8 + t] / 512.f;
        cm[t] = m2; cr[t] = rsqrtf(tmp[12 + t] / 512.f - m2 * m2 + BN_EPS);
    }
    __syncthreads();

    if (t < 64) {
        float v = g_Xrow[n * OO + t];
        int c = t >> 4;
        float y = (v - gm[c]) * gr[c] * bn1w[c] + bn1b[c];
        x1s[t] = y / (1.f + fabsf(y));
    }
    #pragma unroll
    for (int u = 0; u < 2; u++) {
        int i4 = u * 256 + t;
        int c = ((i4 & 15) >> 2);
        float4 q = nbsv[i4];
        float sw = cr[c] * bn1w[c];
        float y;
        y = (q.x - cm[c]) * sw + bn1b[c]; q.x = y / (1.f + fabsf(y));
        y = (q.y - cm[c]) * sw + bn1b[c]; q.y = y / (1.f + fabsf(y));
        y = (q.z - cm[c]) * sw + bn1b[c]; q.z = y / (1.f + fabsf(y));
        y = (q.w - cm[c]) * sw + bn1b[c]; q.w = y / (1.f + fabsf(y));
        nbsv[i4] = q;
    }
    __syncthreads();
    if (t < 64) {
        float a = 0.f;
        #pragma unroll
        for (int k = 0; k < KK; k++) a += nbs[k * 64 + t];
        t2s[t] = a;
    }
    __syncthreads();

    {
        int ai = t >> 4, b = t & 15;
        float sgv[4], ctr[4];
        float den = 1e-7f;
        #pragma unroll
        for (int cc = 0; cc < 4; cc++) {
            float raw = x1s[cc * 16 + ai] * t2s[cc * 16 + b]
                      + x1s[cc * 16 + b]  * t2s[cc * 16 + ai];
            float mag = sqrtf(fmaxf(fabsf(raw), 1e-8f));
            float sg  = (raw > 0.f) ? mag : ((raw < 0.f) ? -mag : 0.f);
            sgv[cc] = sg;
            den += fabsf(sg);
        }
        float inv = 1.f / den;
        #pragma unroll
        for (int cc = 0; cc < 4; cc++)
            ctr[cc] = sgv[cc] * inv * x1s[cc * 16 + b];
        #pragma unroll
        for (int d = 8; d > 0; d >>= 1) {
            #pragma unroll
            for (int cc = 0; cc < 4; cc++)
                ctr[cc] += __shfl_down_sync(0xffffffffu, ctr[cc], d, 16);
        }
        if (b == 0) {
            #pragma unroll
            for (int cc = 0; cc < 4; cc++) xa2s[cc * 16 + ai] = ctr[cc];
        }
    }
    __syncthreads();

    {
        int o = t >> 3, seg = t & 7;
        float acc = 0.f;
        #pragma unroll
        for (int i = seg * 8; i < seg * 8 + 8; i++)
            acc += W2[o * 64 + i] * xa2s[i];
        #pragma unroll
        for (int d = 4; d > 0; d >>= 1)
            acc += __shfl_down_sync(0xffffffffu, acc, d, 8);
        if (seg == 0) g_X2[n * C2c + o] = acc;
    }

    __threadfence();
    __syncthreads();
    if (t == 0) last = (atomicAdd(&g_cnt2[0], 1) == NN - 1);
    __syncthreads();
    if (!last) return;
    __threadfence();

    float* z = nbs;
    for (int i = t; i < NN * C2c; i += 256) z[i] = g_X2[i];
    __syncthreads();

    {
        int q = t & 31, g = t >> 5;
        float s1 = 0.f, s2 = 0.f;
        #pragma unroll
        for (int nn = g * 8; nn < g * 8 + 8; nn++) {
            float v = z[nn * C2c + q];
            s1 += v; s2 += v * v;
        }
        red[q * 8 + g] = s1; red[256 + q * 8 + g] = s2;
    }
    __syncthreads();
    __shared__ float qm[C2c], qr[C2c];
    if (t < C2c) {
        float s1 = 0.f, s2 = 0.f;
        #pragma unroll
        for (int g = 0; g < 8; g++) { s1 += red[t * 8 + g]; s2 += red[256 + t * 8 + g]; }
        float m = s1 / 64.f;
        qm[t] = m; qr[t] = rsqrtf(s2 / 64.f - m * m + BN_EPS);
    }
    __syncthreads();
    for (int i = t; i < NN * C2c; i += 256) {
        int q = i & 31;
        float y = (z[i] - qm[q]) * qr[q] * bn2w[q] + bn2b[q];
        z[i] = y / (1.f + fabsf(y));
    }
    __syncthreads();
    for (int i = t; i < NN * NCLS; i += 256) {
        int nn = i / NCLS, cls = i - nn * NCLS;
        float acc = lb[cls];
        #pragma unroll
        for (int q = 0; q < C2c; q++) acc += z[nn * C2c + q] * lw[cls * C2c + q];
        out[i] = acc;
    }
}

// ============================================================================
extern "C" void kernel_launch(void* const* d_in, const int* in_sizes, int n_in,
                              void* d_out, int out_size)
{
    const float* x    = (const float*)d_in[0];
    const float* nb   = (const float*)d_in[1];
    const float* W1   = (const float*)d_in[2];
    const float* W2   = (const float*)d_in[3];
    const float* bn1w = (const float*)d_in[4];
    const float* bn1b = (const float*)d_in[5];
    const float* bn2w = (const float*)d_in[6];
    const float* bn2b = (const float*)d_in[7];
    const float* lw   = (const float*)d_in[8];
    const float* lb   = (const float*)d_in[9];
    float* out = (float*)d_out;

    k_sort<<<NN, 1024>>>(x, nb);
    dim3 gc(JJ, NN);
    k_cols<<<gc, 1024>>>(x, nb);
    dim3 gg(33, 8);
    k_gemm<<<gg, 256>>>(W1);
    k_layer2<<<NN, 256>>>(W2, bn1w, bn1b, bn2w, bn2b, lw, lb, out);
}